// round 14
// baseline (speedup 1.0000x reference)
#include <cuda_runtime.h>
#include <math.h>
#include <stdint.h>

#define B_ROWS 16384
#define C_CLS  1000
#define NNODES 4096
#define NEDGES 131072

#define NBLK   296                 // 2 blocks/SM x 148 SMs, 512 thr: one wave
#define NWARP  (NBLK * 16)         // 4736

__device__ float2 g_partials[NBLK];
__device__ unsigned int g_ticket = 0;

// 32-byte evict_last load (sm_103a requires .v4.b64 width for this hint).
// Row stride 4000 B = 125 * 32 B, so rows are exactly 125 aligned float8s.
static __device__ __forceinline__ void ldg_keep8(const float* p, float* v) {
    uint64_t a, b, c, d;
    asm volatile("ld.global.nc.L2::evict_last.v4.b64 {%0,%1,%2,%3}, [%4];"
                 : "=l"(a), "=l"(b), "=l"(c), "=l"(d) : "l"(p));
    v[0] = __uint_as_float((uint32_t)a); v[1] = __uint_as_float((uint32_t)(a >> 32));
    v[2] = __uint_as_float((uint32_t)b); v[3] = __uint_as_float((uint32_t)(b >> 32));
    v[4] = __uint_as_float((uint32_t)c); v[5] = __uint_as_float((uint32_t)(c >> 32));
    v[6] = __uint_as_float((uint32_t)d); v[7] = __uint_as_float((uint32_t)(d >> 32));
}

// Per-lane exp-sum of one row (no shfl here — reductions are deferred and
// interleaved by the caller). Two accumulators halve the FADD chain.
static __device__ __forceinline__ float ce_row_sum(const float* r, int lane) {
    float v[4][8];
    #pragma unroll
    for (int k = 0; k < 3; k++) ldg_keep8(r + (lane + 32 * k) * 8, v[k]);
    const bool tail_ok = lane < 29;          // 125 = 3*32 + 29
    if (tail_ok) ldg_keep8(r + (lane + 96) * 8, v[3]);

    float sa = 0.0f, sb = 0.0f;
    #pragma unroll
    for (int k = 0; k < 3; k++) {
        #pragma unroll
        for (int x = 0; x < 4; x++) {
            sa += __expf(v[k][2 * x]);
            sb += __expf(v[k][2 * x + 1]);
        }
    }
    if (tail_ok) {
        #pragma unroll
        for (int x = 0; x < 4; x++) {
            sa += __expf(v[3][2 * x]);
            sb += __expf(v[3][2 * x + 1]);
        }
    }
    return sa + sb;
}

__global__ __launch_bounds__(512, 2) void fused_kernel(const float* __restrict__ outputs,
                                                       const int* __restrict__ targets,
                                                       const float* __restrict__ P,
                                                       const int* __restrict__ src,
                                                       const int* __restrict__ dst,
                                                       float* __restrict__ out) {
    const int t = threadIdx.x;
    const int lane = t & 31;
    const int warp = t >> 5;
    const int gw = blockIdx.x * 16 + warp;  // 0..4735

    const float TWO_PI_F = 6.2831853071795864769f;
    const float PI_F     = 3.1415926535897932385f;

    // ---- cost-balanced static assignment ----
    int nrows, row0, nchunks, chunk0;
    if (gw < 2176)        { nrows = 4; row0 = gw * 4;                    nchunks = 0; chunk0 = 0; }
    else if (gw < 3712)   { nrows = 3; row0 = 8704 + (gw - 2176) * 3;    nchunks = 2; chunk0 = (gw - 2176) * 2; }
    else                  { nrows = 3; row0 = 13312 + (gw - 3712) * 3;   nchunks = 1; chunk0 = 3072 + (gw - 3712); }

    // ---- scattered edge gathers issued first (consumed at the end) ----
    // __ldcs (evict-first): phase sectors must NOT displace the pinned
    // outputs stream in L2 (R12 measured the displacement: +2 us).
    float pa[2], pb[2];
    int si[2], di[2];
    #pragma unroll
    for (int c = 0; c < 2; c++) {
        if (c < nchunks) {
            const int e = (chunk0 + c) * 32 + lane;
            si[c] = __ldg(&src[e]);
            di[c] = __ldg(&dst[e]);
        }
    }
    #pragma unroll
    for (int c = 0; c < 2; c++) {
        if (c < nchunks) {
            pa[c] = __ldcs(&P[(size_t)si[c] * NNODES + di[c]]);
            pb[c] = __ldcs(&P[(size_t)di[c] * NNODES + si[c]]);
        }
    }

    // ---- target-logit gathers issued early ----
    const float* rp[4];
    float xt[4];
    #pragma unroll
    for (int j = 0; j < 4; j++) {
        if (j < nrows) {
            const int row = row0 + j;
            rp[j] = outputs + (size_t)row * C_CLS;
            xt[j] = __ldg(&rp[j][__ldg(&targets[row])]);
        }
    }

    // ---- CE rows: per-lane sums; all shfl reductions deferred + interleaved ----
    float s[4];
    float ce_acc = 0.0f;
    if (nrows == 4) {
        #pragma unroll
        for (int j = 0; j < 4; j++) s[j] = ce_row_sum(rp[j], lane);
        #pragma unroll
        for (int off = 16; off > 0; off >>= 1) {
            #pragma unroll
            for (int j = 0; j < 4; j++)
                s[j] += __shfl_xor_sync(0xFFFFFFFFu, s[j], off);
        }
        #pragma unroll
        for (int j = 0; j < 4; j++) ce_acc += __logf(s[j]) - xt[j];
    } else {
        #pragma unroll
        for (int j = 0; j < 3; j++) s[j] = ce_row_sum(rp[j], lane);
        #pragma unroll
        for (int off = 16; off > 0; off >>= 1) {
            #pragma unroll
            for (int j = 0; j < 3; j++)
                s[j] += __shfl_xor_sync(0xFFFFFFFFu, s[j], off);
        }
        #pragma unroll
        for (int j = 0; j < 3; j++) ce_acc += __logf(s[j]) - xt[j];
    }

    // ---- resonance from the early gathers ----
    float res_acc = 0.0f;
    #pragma unroll
    for (int c = 0; c < 2; c++) {
        if (c < nchunks) {
            float d = fabsf(pa[c] - pb[c]);
            d = fmodf(d, TWO_PI_F);
            if (d > PI_F) d = TWO_PI_F - d;
            res_acc += d;
        }
    }
    #pragma unroll
    for (int off = 16; off > 0; off >>= 1)
        res_acc += __shfl_xor_sync(0xFFFFFFFFu, res_acc, off);

    // ---- block reduce + last-block finalize ----
    __shared__ float s_ce[16], s_res[16];
    __shared__ bool is_last;
    if (lane == 0) { s_ce[warp] = ce_acc; s_res[warp] = res_acc; }
    __syncthreads();

    if (t == 0) {
        float ce = 0.0f, rs = 0.0f;
        #pragma unroll
        for (int w = 0; w < 16; w++) { ce += s_ce[w]; rs += s_res[w]; }
        g_partials[blockIdx.x] = make_float2(ce, rs);
        __threadfence();
        unsigned int ticket = atomicAdd(&g_ticket, 1u);
        is_last = (ticket == NBLK - 1);
    }
    __syncthreads();

    if (is_last) {
        float ce = 0.0f, rs = 0.0f;
        if (t < NBLK) {                       // 296 < 512: one element each
            float2 p = g_partials[t];
            ce = p.x; rs = p.y;
        }
        float vloc = ce * (1.0f / B_ROWS) + 0.1f * rs * (1.0f / NEDGES);

        __shared__ float red[512];
        red[t] = vloc;
        __syncthreads();
        #pragma unroll
        for (int stride = 256; stride > 0; stride >>= 1) {
            if (t < stride) red[t] += red[t + stride];
            __syncthreads();
        }
        if (t == 0) {
            out[0] = red[0];
            g_ticket = 0;     // reset for next graph replay
        }
    }
}

extern "C" void kernel_launch(void* const* d_in, const int* in_sizes, int n_in,
                              void* d_out, int out_size) {
    const float* outputs = (const float*)d_in[0];
    const int*   targets = (const int*)d_in[1];
    const float* phase   = (const float*)d_in[2];
    const int*   esrc    = (const int*)d_in[3];
    const int*   edst    = (const int*)d_in[4];
    float* out = (float*)d_out;

    fused_kernel<<<NBLK, 512>>>(outputs, targets, phase, esrc, edst, out);
}